// round 17
// baseline (speedup 1.0000x reference)
#include <cuda_runtime.h>
#include <cstdint>

// ---------------------------------------------------------------------------
// HexagonalSensor: 16.7M photons -> hex-pixel scatter add (1801 bins)
// R16 (= R15 resubmit after infra failure): reduce-rezeroes-scratch protocol
// (scratch invariantly zero at launch entry -> hex does no zeroing) + 2 CTAs
// share each scratch replica (296 rows, 2.1MB, L2-resident) + MLP-8 one-wave
// reduce. Line-merged REDG scatter (R14) unchanged.
// ---------------------------------------------------------------------------

#define NCTA   592        // 4 CTAs per SM
#define TPB    256
#define PADPIX 1808       // 1801 padded; per-replica row = 7232 B
#define NREP   296        // 2 CTAs per replica
#define ROWCHUNK 8        // rows per reduce block; NREP/ROWCHUNK = 37

// scratch[rep * PADPIX + pix]; zero at every kernel_launch entry
// (zero-init at load, re-zeroed by reduce_kernel each call)
__device__ float g_scratch[NREP * PADPIX];

// ------------------------- per-photon pipeline -----------------------------
__device__ __forceinline__ void photon_one(
    float x, float y, float v,
    float ca, float sa, float ox, float oy,
    float c1, float c2, float c3,
    int R, int twoR, int twoRp3, int fourRp3, int off0R,
    float* __restrict__ my_hist)
{
    // rotate into grid frame
    float xs = x - ox;
    float ys = y - oy;
    float xrot = fmaf(ca, xs, -(sa * ys));
    float yrot = fmaf(sa, xs, ca * ys);

    // cartesian -> axial (constants folded with 1/hex_size)
    float q = fmaf(c1, xrot, c2 * yrot);
    float r = c3 * yrot;
    float s = -q - r;

    // round-half-even via magic add; integer falls out of mantissa bits
    const float MAG = 12582912.0f;           // 1.5 * 2^23
    const int   MAGBITS = 0x4B400000;
    float fq = q + MAG, fr = r + MAG, fs = s + MAG;
    float qr = fq - MAG, rr = fr - MAG, sr = fs - MAG;
    int qi = __float_as_int(fq) - MAGBITS;
    int ri = __float_as_int(fr) - MAGBITS;
    int si = __float_as_int(fs) - MAGBITS;

    // cube-round fixup (faithful to reference _axial_round)
    float qd = fabsf(qr - q), rd = fabsf(rr - r), sd = fabsf(sr - s);
    bool cq = (qd > rd) && (qd > sd);
    bool cr = (rd > qd) && (rd > sd);
    if (cq)      qi = -ri - si;
    else if (cr) ri = -qi - si;

    // analytic hex pixel id (rows q=-R..R, r ascending; verified R7/R8)
    int t = qi + R;
    int u = ri + R;
    int w = qi + ri + R;
    bool valid = ((unsigned)t <= (unsigned)twoR) &
                 ((unsigned)u <= (unsigned)twoR) &
                 ((unsigned)w <= (unsigned)twoR);
    int pixneg = ((t  * (t + twoRp3))  >> 1) + ri;
    int pixpos = ((qi * (fourRp3 - qi)) >> 1) + off0R + ri;
    int pix = (qi <= 0) ? pixneg : pixpos;

    if (valid)
        atomicAdd(my_hist + pix, v);          // RED.E.ADD.F32, 7.2KB footprint
}

__global__ __launch_bounds__(TPB)
void hex_kernel(const float* __restrict__ x,
                const float* __restrict__ y,
                const float* __restrict__ vals,
                const float* __restrict__ p_hs,
                const float* __restrict__ p_rot,
                const float* __restrict__ p_ox,
                const float* __restrict__ p_oy,
                const int* __restrict__ p_qmin,
                int n4, int npix,
                float* __restrict__ out)
{
    // 2 CTAs share one replica row; scratch already zero (invariant)
    float* my_hist = g_scratch + (blockIdx.x >> 1) * PADPIX;

    // CTA 0 zeroes d_out (reduce REDs into it later this call)
    if (blockIdx.x == 0)
        for (int p = threadIdx.x; p < npix; p += TPB)
            out[p] = 0.0f;

    float hs  = *p_hs;
    float rot = *p_rot;
    float ox  = *p_ox;
    float oy  = *p_oy;
    int qmin  = *p_qmin;

    float ca = cosf(-rot), sa = sinf(-rot);
    float inv_hs = 1.0f / hs;
    float c1 = 0.57735026919f * inv_hs;          // (sqrt3/3)/hs
    float c2 = -0.33333333333f * inv_hs;         // -(1/3)/hs
    float c3 = 0.66666666667f * inv_hs;          // (2/3)/hs

    int R       = -qmin;                         // 24
    int twoR    = 2 * R;
    int twoRp3  = 2 * R + 3;
    int fourRp3 = 4 * R + 3;
    int off0R   = R * (R + 1) + ((R * (R - 1)) >> 1) + R;

    const float4* x4 = reinterpret_cast<const float4*>(x);
    const float4* y4 = reinterpret_cast<const float4*>(y);
    const float4* v4 = reinterpret_cast<const float4*>(vals);

    int stride = gridDim.x * blockDim.x;
    for (int i = blockIdx.x * blockDim.x + threadIdx.x; i < n4; i += stride) {
        float4 xx = __ldcs(&x4[i]);     // evict-first: keep scratch resident
        float4 yy = __ldcs(&y4[i]);
        float4 vv = __ldcs(&v4[i]);
        photon_one(xx.x, yy.x, vv.x, ca, sa, ox, oy, c1, c2, c3,
                   R, twoR, twoRp3, fourRp3, off0R, my_hist);
        photon_one(xx.y, yy.y, vv.y, ca, sa, ox, oy, c1, c2, c3,
                   R, twoR, twoRp3, fourRp3, off0R, my_hist);
        photon_one(xx.z, yy.z, vv.z, ca, sa, ox, oy, c1, c2, c3,
                   R, twoR, twoRp3, fourRp3, off0R, my_hist);
        photon_one(xx.w, yy.w, vv.w, ca, sa, ox, oy, c1, c2, c3,
                   R, twoR, twoRp3, fourRp3, off0R, my_hist);
    }
}

// -------- reduce + rezero: 37 row-chunks x 8 pixel-blocks, MLP 8 -----------
// Each thread: 8 independent loads (one per row in its chunk), RED the sum
// into out[pix], then store zeros back so scratch is zero for the next call.
__global__ __launch_bounds__(256)
void reduce_kernel(float* __restrict__ out, int npix) {
    int pb  = blockIdx.x & 7;           // pixel block 0..7
    int g   = blockIdx.x >> 3;          // row chunk 0..36
    int pix = pb * 256 + threadIdx.x;
    if (pix >= npix) return;

    float* base = g_scratch + (size_t)g * ROWCHUNK * PADPIX + pix;

    float v[ROWCHUNK];
    #pragma unroll
    for (int c = 0; c < ROWCHUNK; c++)          // 8 loads in flight (MLP 8)
        v[c] = base[c * PADPIX];

    float s = ((v[0] + v[1]) + (v[2] + v[3])) +
              ((v[4] + v[5]) + (v[6] + v[7]));
    atomicAdd(out + pix, s);                    // out pre-zeroed by hex CTA 0

    #pragma unroll
    for (int c = 0; c < ROWCHUNK; c++)          // restore the zero invariant
        base[c * PADPIX] = 0.0f;
}

// ------------------------------ launch -------------------------------------
extern "C" void kernel_launch(void* const* d_in, const int* in_sizes, int n_in,
                              void* d_out, int out_size)
{
    const float* x    = (const float*)d_in[0];
    const float* y    = (const float*)d_in[1];
    const float* vals = (const float*)d_in[2];
    const float* hs   = (const float*)d_in[4];
    const float* rot  = (const float*)d_in[5];
    const float* ox   = (const float*)d_in[6];
    const float* oy   = (const float*)d_in[7];
    const int*   qmin = (const int*)  d_in[8];

    int n = in_sizes[0];
    int npix = out_size;                 // 1801
    if (npix > PADPIX) npix = PADPIX;

    hex_kernel<<<NCTA, TPB>>>(x, y, vals, hs, rot, ox, oy, qmin,
                              n / 4, npix, (float*)d_out);
    reduce_kernel<<<(NREP / ROWCHUNK) * 8, 256>>>((float*)d_out, npix);
}